// round 12
// baseline (speedup 1.0000x reference)
#include <cuda_runtime.h>
#include <math.h>

// ---------------------------------------------------------------------------
// out[i,j,k] = trilinear(vol, T @ [i,j,k,1]) with zero outside bounds.
// R6 -> R7: same 4-voxels/thread-along-j tiling, but loads-first structure:
// all 32 tap LDGs issue before any interpolation math, so the loads actually
// overlap (R6 serialized at 32 regs). launch_bounds(256,4) allows 64 regs.
// ---------------------------------------------------------------------------

#define D_DIM 256
#define H_DIM 256
#define W_DIM 256

__device__ float g_T[12];      // written by setup kernel
__constant__ float c_T[12];    // read by main kernel (c-bank)

__device__ __forceinline__ void mat4_mul(const float* A, const float* B, float* C) {
    for (int r = 0; r < 4; ++r)
        for (int c = 0; c < 4; ++c) {
            float s = 0.f;
            for (int m = 0; m < 4; ++m) s += A[r * 4 + m] * B[m * 4 + c];
            C[r * 4 + c] = s;
        }
}

__device__ void mat4_inv(const float* m, float* inv) {
    inv[0]  =  m[5]*m[10]*m[15] - m[5]*m[11]*m[14] - m[9]*m[6]*m[15] + m[9]*m[7]*m[14] + m[13]*m[6]*m[11] - m[13]*m[7]*m[10];
    inv[4]  = -m[4]*m[10]*m[15] + m[4]*m[11]*m[14] + m[8]*m[6]*m[15] - m[8]*m[7]*m[14] - m[12]*m[6]*m[11] + m[12]*m[7]*m[10];
    inv[8]  =  m[4]*m[9]*m[15]  - m[4]*m[11]*m[13] - m[8]*m[5]*m[15] + m[8]*m[7]*m[13] + m[12]*m[5]*m[11] - m[12]*m[7]*m[9];
    inv[12] = -m[4]*m[9]*m[14]  + m[4]*m[10]*m[13] + m[8]*m[5]*m[14] - m[8]*m[6]*m[13] - m[12]*m[5]*m[10] + m[12]*m[6]*m[9];
    inv[1]  = -m[1]*m[10]*m[15] + m[1]*m[11]*m[14] + m[9]*m[2]*m[15] - m[9]*m[3]*m[14] - m[13]*m[2]*m[11] + m[13]*m[3]*m[10];
    inv[5]  =  m[0]*m[10]*m[15] - m[0]*m[11]*m[14] - m[8]*m[2]*m[15] + m[8]*m[3]*m[14] + m[12]*m[2]*m[11] - m[12]*m[3]*m[10];
    inv[9]  = -m[0]*m[9]*m[15]  + m[0]*m[11]*m[13] + m[8]*m[1]*m[15] - m[8]*m[3]*m[13] - m[12]*m[1]*m[11] + m[12]*m[3]*m[9];
    inv[13] =  m[0]*m[9]*m[14]  - m[0]*m[10]*m[13] - m[8]*m[1]*m[14] + m[8]*m[2]*m[13] + m[12]*m[1]*m[10] - m[12]*m[2]*m[9];
    inv[2]  =  m[1]*m[6]*m[15]  - m[1]*m[7]*m[14]  - m[5]*m[2]*m[15] + m[5]*m[3]*m[14] + m[13]*m[2]*m[7]  - m[13]*m[3]*m[6];
    inv[6]  = -m[0]*m[6]*m[15]  + m[0]*m[7]*m[14]  + m[4]*m[2]*m[15] - m[4]*m[3]*m[14] - m[12]*m[2]*m[7]  + m[12]*m[3]*m[6];
    inv[10] =  m[0]*m[5]*m[15]  - m[0]*m[7]*m[13]  - m[4]*m[1]*m[15] + m[4]*m[3]*m[13] + m[12]*m[1]*m[7]  - m[12]*m[3]*m[5];
    inv[14] = -m[0]*m[5]*m[14]  + m[0]*m[6]*m[13]  + m[4]*m[1]*m[14] - m[4]*m[2]*m[13] - m[12]*m[1]*m[6]  + m[12]*m[2]*m[5];
    inv[3]  = -m[1]*m[6]*m[11]  + m[1]*m[7]*m[10]  + m[5]*m[2]*m[11] - m[5]*m[3]*m[10] - m[9]*m[2]*m[7]   + m[9]*m[3]*m[6];
    inv[7]  =  m[0]*m[6]*m[11]  - m[0]*m[7]*m[10]  - m[4]*m[2]*m[11] + m[4]*m[3]*m[10] + m[8]*m[2]*m[7]   - m[8]*m[3]*m[6];
    inv[11] = -m[0]*m[5]*m[11]  + m[0]*m[7]*m[9]   + m[4]*m[1]*m[11] - m[4]*m[3]*m[9]  - m[8]*m[1]*m[7]   + m[8]*m[3]*m[5];
    inv[15] =  m[0]*m[5]*m[10]  - m[0]*m[6]*m[9]   - m[4]*m[1]*m[10] + m[4]*m[2]*m[9]  + m[8]*m[1]*m[6]   - m[8]*m[2]*m[5];
    float det = m[0]*inv[0] + m[1]*inv[4] + m[2]*inv[8] + m[3]*inv[12];
    float id = 1.0f / det;
    for (int i = 0; i < 16; ++i) inv[i] *= id;
}

__global__ void compute_T_kernel(const float* __restrict__ angle,
                                 const float* __restrict__ trans,
                                 const float* __restrict__ ref_v2r,
                                 const float* __restrict__ flo_v2r,
                                 const float* __restrict__ cog) {
    if (threadIdx.x != 0 || blockIdx.x != 0) return;

    float ax = angle[0], ay = angle[1], az = angle[2];
    float cx = cosf(ax), sx = sinf(ax);
    float cy = cosf(ay), sy = sinf(ay);
    float cz = cosf(az), sz = sinf(az);

    float Rx[9] = {1, 0, 0, 0, cx, -sx, 0, sx, cx};
    float Ry[9] = {cy, 0, sy, 0, 1, 0, -sy, 0, cy};
    float Rz[9] = {cz, -sz, 0, sz, cz, 0, 0, 0, 1};
    float Rxy[9], R[9];
    for (int r = 0; r < 3; ++r)
        for (int c = 0; c < 3; ++c) {
            float s = 0.f;
            for (int m = 0; m < 3; ++m) s += Rx[r*3+m] * Ry[m*3+c];
            Rxy[r*3+c] = s;
        }
    for (int r = 0; r < 3; ++r)
        for (int c = 0; c < 3; ++c) {
            float s = 0.f;
            for (int m = 0; m < 3; ++m) s += Rxy[r*3+m] * Rz[m*3+c];
            R[r*3+c] = s;
        }

    float Tc[16]  = {1,0,0,-cog[0], 0,1,0,-cog[1], 0,0,1,-cog[2], 0,0,0,1};
    float Tci[16] = {1,0,0, cog[0], 0,1,0, cog[1], 0,0,1, cog[2], 0,0,0,1};
    float Tt[16]  = {1,0,0,trans[0], 0,1,0,trans[1], 0,0,1,trans[2], 0,0,0,1};
    float Tr[16]  = {R[0],R[1],R[2],0, R[3],R[4],R[5],0, R[6],R[7],R[8],0, 0,0,0,1};

    float tmp1[16], tmp2[16], Trig[16];
    mat4_mul(Tr, Tc, tmp1);
    mat4_mul(Tt, tmp1, tmp2);
    mat4_mul(Tci, tmp2, Trig);

    float flo_inv[16];
    mat4_inv(flo_v2r, flo_inv);

    float tmp3[16], T[16];
    mat4_mul(Trig, ref_v2r, tmp3);
    mat4_mul(flo_inv, tmp3, T);

    for (int r = 0; r < 3; ++r)
        for (int c = 0; c < 4; ++c)
            g_T[r * 4 + c] = T[r * 4 + c];
}

#define NV 4  // voxels per thread along j

// ---- main kernel: lane == k, 4 voxels/thread along j, loads-first ----
__global__ void __launch_bounds__(256, 4)
quadj_trilinear_kernel(const float* __restrict__ vol, float* __restrict__ out) {
    const int k  = threadIdx.x;           // 0..255, lane-contiguous
    const int j0 = blockIdx.y * NV;       // 0,4,...,252
    const int i  = blockIdx.z;            // 0..255

    const float fi_in = (float)i, fj_in = (float)j0, fk_in = (float)k;

    const float di0 = fmaf(c_T[0], fi_in, fmaf(c_T[1], fj_in, fmaf(c_T[2],  fk_in, c_T[3])));
    const float dj0 = fmaf(c_T[4], fi_in, fmaf(c_T[5], fj_in, fmaf(c_T[6],  fk_in, c_T[7])));
    const float dk0 = fmaf(c_T[8], fi_in, fmaf(c_T[9], fj_in, fmaf(c_T[10], fk_in, c_T[11])));
    const float sA = c_T[1], sB = c_T[5], sC = c_T[9];

    // ---- phase 1: coordinates, bounds, addresses for all NV voxels ----
    bool  ok[NV];
    float wi[NV], wj[NV], wk[NV];
    int   b_ff[NV], b_fc[NV], b_cf[NV], b_cc[NV], dko[NV];

#pragma unroll
    for (int v = 0; v < NV; ++v) {
        const float fv = (float)v;
        float di = fmaf(fv, sA, di0);
        float dj = fmaf(fv, sB, dj0);
        float dk = fmaf(fv, sC, dk0);

        const float mx = fmaxf(fmaxf(fabsf(di - 127.5f), fabsf(dj - 127.5f)),
                               fabsf(dk - 127.5f));
        ok[v] = (mx <= 127.5f);

        di = ok[v] ? di : 0.f;
        dj = ok[v] ? dj : 0.f;
        dk = ok[v] ? dk : 0.f;

        const int fi = __float2int_rd(di);
        const int fj = __float2int_rd(dj);
        const int fk = __float2int_rd(dk);

        wi[v] = di - (float)fi;
        wj[v] = dj - (float)fj;
        wk[v] = dk - (float)fk;

        const int dio = (fi < 255) ? 1 : 0;
        const int djo = (fj < 255) ? 1 : 0;
        dko[v] = (fk < 255) ? 1 : 0;

        b_ff[v] = (fi * H_DIM + fj) * W_DIM + fk;
        b_fc[v] = b_ff[v] + djo * W_DIM;
        b_cf[v] = b_ff[v] + dio * (H_DIM * W_DIM);
        b_cc[v] = b_cf[v] + djo * W_DIM;
    }

    // ---- phase 2: all 8*NV loads issue back-to-back ----
    float t0[NV], t1[NV], t2[NV], t3[NV], t4[NV], t5[NV], t6[NV], t7[NV];
#pragma unroll
    for (int v = 0; v < NV; ++v) {
        t0[v] = __ldg(vol + b_ff[v]);
        t1[v] = __ldg(vol + b_ff[v] + dko[v]);
        t2[v] = __ldg(vol + b_fc[v]);
        t3[v] = __ldg(vol + b_fc[v] + dko[v]);
        t4[v] = __ldg(vol + b_cf[v]);
        t5[v] = __ldg(vol + b_cf[v] + dko[v]);
        t6[v] = __ldg(vol + b_cc[v]);
        t7[v] = __ldg(vol + b_cc[v] + dko[v]);
    }

    // ---- phase 3: interpolation + stores ----
    const int o0 = (i * H_DIM + j0) * W_DIM + k;
#pragma unroll
    for (int v = 0; v < NV; ++v) {
        const float c00 = fmaf(wk[v], t1[v] - t0[v], t0[v]);
        const float c01 = fmaf(wk[v], t3[v] - t2[v], t2[v]);
        const float c10 = fmaf(wk[v], t5[v] - t4[v], t4[v]);
        const float c11 = fmaf(wk[v], t7[v] - t6[v], t6[v]);
        const float c0  = fmaf(wj[v], c01 - c00, c00);
        const float c1  = fmaf(wj[v], c11 - c10, c10);
        float r         = fmaf(wi[v], c1 - c0, c0);
        r = ok[v] ? r : 0.f;
        __stcs(out + o0 + v * W_DIM, r);
    }
}

extern "C" void kernel_launch(void* const* d_in, const int* in_sizes, int n_in,
                              void* d_out, int out_size) {
    const float* image   = (const float*)d_in[0];
    const float* angle   = (const float*)d_in[1];
    const float* trans   = (const float*)d_in[2];
    const float* ref_v2r = (const float*)d_in[3];
    const float* flo_v2r = (const float*)d_in[4];
    const float* cog     = (const float*)d_in[5];
    float* out = (float*)d_out;

    compute_T_kernel<<<1, 1>>>(angle, trans, ref_v2r, flo_v2r, cog);

    void* g_T_addr = nullptr;
    cudaGetSymbolAddress(&g_T_addr, g_T);
    cudaMemcpyToSymbolAsync(c_T, g_T_addr, 12 * sizeof(float), 0,
                            cudaMemcpyDeviceToDevice, 0);

    dim3 block(256, 1, 1);
    dim3 grid(1, H_DIM / NV, D_DIM);
    quadj_trilinear_kernel<<<grid, block>>>(image, out);
}

// round 13
// speedup vs baseline: 1.0140x; 1.0140x over previous
#include <cuda_runtime.h>
#include <math.h>

// ---------------------------------------------------------------------------
// out[i,j,k] = trilinear(vol, T @ [i,j,k,1]) with zero outside bounds.
// R6 -> R7: same 4-voxels/thread-along-j tiling, but loads-first structure:
// all 32 tap LDGs issue before any interpolation math, so the loads actually
// overlap (R6 serialized at 32 regs). launch_bounds(256,4) allows 64 regs.
// ---------------------------------------------------------------------------

#define D_DIM 256
#define H_DIM 256
#define W_DIM 256

__device__ float g_T[12];      // written by setup kernel
__constant__ float c_T[12];    // read by main kernel (c-bank)

__device__ __forceinline__ void mat4_mul(const float* A, const float* B, float* C) {
    for (int r = 0; r < 4; ++r)
        for (int c = 0; c < 4; ++c) {
            float s = 0.f;
            for (int m = 0; m < 4; ++m) s += A[r * 4 + m] * B[m * 4 + c];
            C[r * 4 + c] = s;
        }
}

__device__ void mat4_inv(const float* m, float* inv) {
    inv[0]  =  m[5]*m[10]*m[15] - m[5]*m[11]*m[14] - m[9]*m[6]*m[15] + m[9]*m[7]*m[14] + m[13]*m[6]*m[11] - m[13]*m[7]*m[10];
    inv[4]  = -m[4]*m[10]*m[15] + m[4]*m[11]*m[14] + m[8]*m[6]*m[15] - m[8]*m[7]*m[14] - m[12]*m[6]*m[11] + m[12]*m[7]*m[10];
    inv[8]  =  m[4]*m[9]*m[15]  - m[4]*m[11]*m[13] - m[8]*m[5]*m[15] + m[8]*m[7]*m[13] + m[12]*m[5]*m[11] - m[12]*m[7]*m[9];
    inv[12] = -m[4]*m[9]*m[14]  + m[4]*m[10]*m[13] + m[8]*m[5]*m[14] - m[8]*m[6]*m[13] - m[12]*m[5]*m[10] + m[12]*m[6]*m[9];
    inv[1]  = -m[1]*m[10]*m[15] + m[1]*m[11]*m[14] + m[9]*m[2]*m[15] - m[9]*m[3]*m[14] - m[13]*m[2]*m[11] + m[13]*m[3]*m[10];
    inv[5]  =  m[0]*m[10]*m[15] - m[0]*m[11]*m[14] - m[8]*m[2]*m[15] + m[8]*m[3]*m[14] + m[12]*m[2]*m[11] - m[12]*m[3]*m[10];
    inv[9]  = -m[0]*m[9]*m[15]  + m[0]*m[11]*m[13] + m[8]*m[1]*m[15] - m[8]*m[3]*m[13] - m[12]*m[1]*m[11] + m[12]*m[3]*m[9];
    inv[13] =  m[0]*m[9]*m[14]  - m[0]*m[10]*m[13] - m[8]*m[1]*m[14] + m[8]*m[2]*m[13] + m[12]*m[1]*m[10] - m[12]*m[2]*m[9];
    inv[2]  =  m[1]*m[6]*m[15]  - m[1]*m[7]*m[14]  - m[5]*m[2]*m[15] + m[5]*m[3]*m[14] + m[13]*m[2]*m[7]  - m[13]*m[3]*m[6];
    inv[6]  = -m[0]*m[6]*m[15]  + m[0]*m[7]*m[14]  + m[4]*m[2]*m[15] - m[4]*m[3]*m[14] - m[12]*m[2]*m[7]  + m[12]*m[3]*m[6];
    inv[10] =  m[0]*m[5]*m[15]  - m[0]*m[7]*m[13]  - m[4]*m[1]*m[15] + m[4]*m[3]*m[13] + m[12]*m[1]*m[7]  - m[12]*m[3]*m[5];
    inv[14] = -m[0]*m[5]*m[14]  + m[0]*m[6]*m[13]  + m[4]*m[1]*m[14] - m[4]*m[2]*m[13] - m[12]*m[1]*m[6]  + m[12]*m[2]*m[5];
    inv[3]  = -m[1]*m[6]*m[11]  + m[1]*m[7]*m[10]  + m[5]*m[2]*m[11] - m[5]*m[3]*m[10] - m[9]*m[2]*m[7]   + m[9]*m[3]*m[6];
    inv[7]  =  m[0]*m[6]*m[11]  - m[0]*m[7]*m[10]  - m[4]*m[2]*m[11] + m[4]*m[3]*m[10] + m[8]*m[2]*m[7]   - m[8]*m[3]*m[6];
    inv[11] = -m[0]*m[5]*m[11]  + m[0]*m[7]*m[9]   + m[4]*m[1]*m[11] - m[4]*m[3]*m[9]  - m[8]*m[1]*m[7]   + m[8]*m[3]*m[5];
    inv[15] =  m[0]*m[5]*m[10]  - m[0]*m[6]*m[9]   - m[4]*m[1]*m[10] + m[4]*m[2]*m[9]  + m[8]*m[1]*m[6]   - m[8]*m[2]*m[5];
    float det = m[0]*inv[0] + m[1]*inv[4] + m[2]*inv[8] + m[3]*inv[12];
    float id = 1.0f / det;
    for (int i = 0; i < 16; ++i) inv[i] *= id;
}

__global__ void compute_T_kernel(const float* __restrict__ angle,
                                 const float* __restrict__ trans,
                                 const float* __restrict__ ref_v2r,
                                 const float* __restrict__ flo_v2r,
                                 const float* __restrict__ cog) {
    if (threadIdx.x != 0 || blockIdx.x != 0) return;

    float ax = angle[0], ay = angle[1], az = angle[2];
    float cx = cosf(ax), sx = sinf(ax);
    float cy = cosf(ay), sy = sinf(ay);
    float cz = cosf(az), sz = sinf(az);

    float Rx[9] = {1, 0, 0, 0, cx, -sx, 0, sx, cx};
    float Ry[9] = {cy, 0, sy, 0, 1, 0, -sy, 0, cy};
    float Rz[9] = {cz, -sz, 0, sz, cz, 0, 0, 0, 1};
    float Rxy[9], R[9];
    for (int r = 0; r < 3; ++r)
        for (int c = 0; c < 3; ++c) {
            float s = 0.f;
            for (int m = 0; m < 3; ++m) s += Rx[r*3+m] * Ry[m*3+c];
            Rxy[r*3+c] = s;
        }
    for (int r = 0; r < 3; ++r)
        for (int c = 0; c < 3; ++c) {
            float s = 0.f;
            for (int m = 0; m < 3; ++m) s += Rxy[r*3+m] * Rz[m*3+c];
            R[r*3+c] = s;
        }

    float Tc[16]  = {1,0,0,-cog[0], 0,1,0,-cog[1], 0,0,1,-cog[2], 0,0,0,1};
    float Tci[16] = {1,0,0, cog[0], 0,1,0, cog[1], 0,0,1, cog[2], 0,0,0,1};
    float Tt[16]  = {1,0,0,trans[0], 0,1,0,trans[1], 0,0,1,trans[2], 0,0,0,1};
    float Tr[16]  = {R[0],R[1],R[2],0, R[3],R[4],R[5],0, R[6],R[7],R[8],0, 0,0,0,1};

    float tmp1[16], tmp2[16], Trig[16];
    mat4_mul(Tr, Tc, tmp1);
    mat4_mul(Tt, tmp1, tmp2);
    mat4_mul(Tci, tmp2, Trig);

    float flo_inv[16];
    mat4_inv(flo_v2r, flo_inv);

    float tmp3[16], T[16];
    mat4_mul(Trig, ref_v2r, tmp3);
    mat4_mul(flo_inv, tmp3, T);

    for (int r = 0; r < 3; ++r)
        for (int c = 0; c < 4; ++c)
            g_T[r * 4 + c] = T[r * 4 + c];
}

#define NV 4  // voxels per thread along j

// ---- main kernel: lane == k, 4 voxels/thread along j, loads-first ----
__global__ void __launch_bounds__(256, 4)
quadj_trilinear_kernel(const float* __restrict__ vol, float* __restrict__ out) {
    const int k  = threadIdx.x;           // 0..255, lane-contiguous
    const int j0 = blockIdx.y * NV;       // 0,4,...,252
    const int i  = blockIdx.z;            // 0..255

    const float fi_in = (float)i, fj_in = (float)j0, fk_in = (float)k;

    const float di0 = fmaf(c_T[0], fi_in, fmaf(c_T[1], fj_in, fmaf(c_T[2],  fk_in, c_T[3])));
    const float dj0 = fmaf(c_T[4], fi_in, fmaf(c_T[5], fj_in, fmaf(c_T[6],  fk_in, c_T[7])));
    const float dk0 = fmaf(c_T[8], fi_in, fmaf(c_T[9], fj_in, fmaf(c_T[10], fk_in, c_T[11])));
    const float sA = c_T[1], sB = c_T[5], sC = c_T[9];

    // ---- phase 1: coordinates, bounds, addresses for all NV voxels ----
    bool  ok[NV];
    float wi[NV], wj[NV], wk[NV];
    int   b_ff[NV], b_fc[NV], b_cf[NV], b_cc[NV], dko[NV];

#pragma unroll
    for (int v = 0; v < NV; ++v) {
        const float fv = (float)v;
        float di = fmaf(fv, sA, di0);
        float dj = fmaf(fv, sB, dj0);
        float dk = fmaf(fv, sC, dk0);

        const float mx = fmaxf(fmaxf(fabsf(di - 127.5f), fabsf(dj - 127.5f)),
                               fabsf(dk - 127.5f));
        ok[v] = (mx <= 127.5f);

        di = ok[v] ? di : 0.f;
        dj = ok[v] ? dj : 0.f;
        dk = ok[v] ? dk : 0.f;

        const int fi = __float2int_rd(di);
        const int fj = __float2int_rd(dj);
        const int fk = __float2int_rd(dk);

        wi[v] = di - (float)fi;
        wj[v] = dj - (float)fj;
        wk[v] = dk - (float)fk;

        const int dio = (fi < 255) ? 1 : 0;
        const int djo = (fj < 255) ? 1 : 0;
        dko[v] = (fk < 255) ? 1 : 0;

        b_ff[v] = (fi * H_DIM + fj) * W_DIM + fk;
        b_fc[v] = b_ff[v] + djo * W_DIM;
        b_cf[v] = b_ff[v] + dio * (H_DIM * W_DIM);
        b_cc[v] = b_cf[v] + djo * W_DIM;
    }

    // ---- phase 2: all 8*NV loads issue back-to-back ----
    float t0[NV], t1[NV], t2[NV], t3[NV], t4[NV], t5[NV], t6[NV], t7[NV];
#pragma unroll
    for (int v = 0; v < NV; ++v) {
        t0[v] = __ldg(vol + b_ff[v]);
        t1[v] = __ldg(vol + b_ff[v] + dko[v]);
        t2[v] = __ldg(vol + b_fc[v]);
        t3[v] = __ldg(vol + b_fc[v] + dko[v]);
        t4[v] = __ldg(vol + b_cf[v]);
        t5[v] = __ldg(vol + b_cf[v] + dko[v]);
        t6[v] = __ldg(vol + b_cc[v]);
        t7[v] = __ldg(vol + b_cc[v] + dko[v]);
    }

    // ---- phase 3: interpolation + stores ----
    const int o0 = (i * H_DIM + j0) * W_DIM + k;
#pragma unroll
    for (int v = 0; v < NV; ++v) {
        const float c00 = fmaf(wk[v], t1[v] - t0[v], t0[v]);
        const float c01 = fmaf(wk[v], t3[v] - t2[v], t2[v]);
        const float c10 = fmaf(wk[v], t5[v] - t4[v], t4[v]);
        const float c11 = fmaf(wk[v], t7[v] - t6[v], t6[v]);
        const float c0  = fmaf(wj[v], c01 - c00, c00);
        const float c1  = fmaf(wj[v], c11 - c10, c10);
        float r         = fmaf(wi[v], c1 - c0, c0);
        r = ok[v] ? r : 0.f;
        __stcs(out + o0 + v * W_DIM, r);
    }
}

extern "C" void kernel_launch(void* const* d_in, const int* in_sizes, int n_in,
                              void* d_out, int out_size) {
    const float* image   = (const float*)d_in[0];
    const float* angle   = (const float*)d_in[1];
    const float* trans   = (const float*)d_in[2];
    const float* ref_v2r = (const float*)d_in[3];
    const float* flo_v2r = (const float*)d_in[4];
    const float* cog     = (const float*)d_in[5];
    float* out = (float*)d_out;

    compute_T_kernel<<<1, 1>>>(angle, trans, ref_v2r, flo_v2r, cog);

    void* g_T_addr = nullptr;
    cudaGetSymbolAddress(&g_T_addr, g_T);
    cudaMemcpyToSymbolAsync(c_T, g_T_addr, 12 * sizeof(float), 0,
                            cudaMemcpyDeviceToDevice, 0);

    dim3 block(256, 1, 1);
    dim3 grid(1, H_DIM / NV, D_DIM);
    quadj_trilinear_kernel<<<grid, block>>>(image, out);
}